// round 4
// baseline (speedup 1.0000x reference)
#include <cuda_runtime.h>

// RVOModule on GB300. v_next = v_desire + 0.2 * sum_k normal_k.
// B=256, N=1024, K=32.
// R4: thread-per-pedestrian + smem staging (as R3), but fast-math:
//   - squared-distance collision test (kills one sqrt)
//   - rsqrt.approx for the normal (kills sqrt+divide chain)
//   - __fdividef for t (approx rcp)

#define TAU 3.0f
#define FIX 0.2f

#define NPED 1024
#define KNEI 32
#define BLOCKS_PER_BATCH 4
#define THREADS 256                                   // peds per block

__device__ __forceinline__ float rsqrt_approx(float x) {
    float r;
    asm("rsqrt.approx.f32 %0, %1;" : "=f"(r) : "f"(x));
    return r;
}

__global__ __launch_bounds__(THREADS)
void rvo_kernel(const float2* __restrict__ p_cur,
                const float2* __restrict__ v_cur,
                const float2* __restrict__ v_desire,
                const int*    __restrict__ near_idx,
                const float*  __restrict__ neigh_mask,
                const int*    __restrict__ thr_ptr,
                float2*       __restrict__ out)
{
    __shared__ float4 pv[NPED];   // {p.x, p.y, v.x, v.y}, 16 KB

    const int b    = blockIdx.x / BLOCKS_PER_BATCH;
    const int sub  = blockIdx.x % BLOCKS_PER_BATCH;
    const int base = b * NPED;

    // Stage this batch's positions+velocities (coalesced float2 reads).
    #pragma unroll
    for (int i = threadIdx.x; i < NPED; i += THREADS) {
        const float2 p = p_cur[base + i];
        const float2 v = v_cur[base + i];
        pv[i] = make_float4(p.x, p.y, v.x, v.y);
    }
    __syncthreads();

    const int n = sub * THREADS + threadIdx.x;   // pedestrian within batch
    const int g = base + n;                      // global pedestrian id

    const float thrF = (float)(*thr_ptr);
    const float thr2 = thrF * thrF;
    const float4 self = pv[n];
    const float2 vd   = v_desire[g];

    // 128B-aligned vector views of this pedestrian's neighbor lists
    const int4*   idx4 = (const int4*)  (near_idx   + (long long)g * KNEI);
    const float4* msk4 = (const float4*)(neigh_mask + (long long)g * KNEI);

    float cx = 0.0f, cy = 0.0f;

    #pragma unroll
    for (int q = 0; q < KNEI / 4; ++q) {
        const int4   j4 = idx4[q];
        const float4 m4 = msk4[q];

        const int   js[4] = { j4.x, j4.y, j4.z, j4.w };
        const float ms[4] = { m4.x, m4.y, m4.z, m4.w };

        #pragma unroll
        for (int u = 0; u < 4; ++u) {
            const float m = ms[u];
            const float4 qv = pv[js[u]];          // LDS.128 gather

            const float rpx = self.x - qv.x * m;
            const float rpy = self.y - qv.y * m;
            const float rvx = vd.x   - qv.z * m;
            const float rvy = vd.y   - qv.w * m;

            const float dpv = rpx * rvx + rpy * rvy;
            const float dvv = rvx * rvx + rvy * rvy + 1e-6f;   // ref: +1e-6
            float t = __fdividef(dpv, dvv + 1e-6f);            // ref: second +1e-6
            t = fminf(fmaxf(t, 0.0f), TAU);

            const float dx = rpx + t * rvx;
            const float dy = rpy + t * rvy;
            const float md2 = dx * dx + dy * dy;   // squared min_dist

            const float s = rpx * rpx + rpy * rpy; // squared |rel_pos|

            // reference: coll = (sqrt(md2) < thr) && (m != 0)
            //            normal = (-rpy, rpx) / (sqrt(s)+1e-6) when coll else 0
            // s == 0 (self-neighbor) => numerator 0 in reference => contribute 0.
            const bool coll = (md2 < thr2) && (m != 0.0f) && (s > 0.0f);
            const float inv = coll ? rsqrt_approx(s) : 0.0f;

            cx -= rpy * inv;
            cy += rpx * inv;
        }
    }

    out[g] = make_float2(vd.x + cx * FIX, vd.y + cy * FIX);
}

extern "C" void kernel_launch(void* const* d_in, const int* in_sizes, int n_in,
                              void* d_out, int out_size)
{
    const float2* p_cur    = (const float2*)d_in[0];
    const float2* v_cur    = (const float2*)d_in[1];
    const float2* v_desire = (const float2*)d_in[2];
    const int*    near_idx = (const int*)d_in[3];
    const float*  mask     = (const float*)d_in[4];
    const int*    thr      = (const int*)d_in[5];
    float2*       out      = (float2*)d_out;

    const int P = in_sizes[0] / 2;               // B*N pedestrians
    const int nBatches = P / NPED;               // 256
    const int blocks = nBatches * BLOCKS_PER_BATCH;

    rvo_kernel<<<blocks, THREADS>>>(p_cur, v_cur, v_desire, near_idx, mask, thr, out);
}

// round 5
// speedup vs baseline: 1.5091x; 1.5091x over previous
#include <cuda_runtime.h>

// RVOModule on GB300. v_next = v_desire + 0.2 * sum_k normal_k.
// B=256, N=1024, K=32.
// R5 = R3's memory/launch config (512 thr, 2 blocks/batch, smem-staged float4,
// thread-per-pedestrian) + R4's fast math (sq-dist test, rsqrt.approx, fdividef).

#define TAU 3.0f
#define FIX 0.2f

#define NPED 1024
#define KNEI 32
#define BLOCKS_PER_BATCH 2
#define THREADS 512                                    // peds per block

__device__ __forceinline__ float rsqrt_approx(float x) {
    float r;
    asm("rsqrt.approx.f32 %0, %1;" : "=f"(r) : "f"(x));
    return r;
}

__global__ __launch_bounds__(THREADS, 2)
void rvo_kernel(const float2* __restrict__ p_cur,
                const float2* __restrict__ v_cur,
                const float2* __restrict__ v_desire,
                const int*    __restrict__ near_idx,
                const float*  __restrict__ neigh_mask,
                const int*    __restrict__ thr_ptr,
                float2*       __restrict__ out)
{
    __shared__ float4 pv[NPED];   // {p.x, p.y, v.x, v.y}, 16 KB

    const int b    = blockIdx.x / BLOCKS_PER_BATCH;
    const int sub  = blockIdx.x % BLOCKS_PER_BATCH;
    const int base = b * NPED;

    // Stage this batch's positions+velocities (coalesced float2 reads).
    #pragma unroll
    for (int i = threadIdx.x; i < NPED; i += THREADS) {
        const float2 p = p_cur[base + i];
        const float2 v = v_cur[base + i];
        pv[i] = make_float4(p.x, p.y, v.x, v.y);
    }
    __syncthreads();

    const int n = sub * THREADS + threadIdx.x;   // pedestrian within batch
    const int g = base + n;                      // global pedestrian id

    const float thrF = (float)(*thr_ptr);
    const float thr2 = thrF * thrF;
    const float4 self = pv[n];
    const float2 vd   = v_desire[g];

    // 128B-aligned vector views of this pedestrian's neighbor lists
    const int4*   idx4 = (const int4*)  (near_idx   + (long long)g * KNEI);
    const float4* msk4 = (const float4*)(neigh_mask + (long long)g * KNEI);

    float cx = 0.0f, cy = 0.0f;

    #pragma unroll
    for (int q = 0; q < KNEI / 4; ++q) {
        const int4   j4 = idx4[q];
        const float4 m4 = msk4[q];

        const int   js[4] = { j4.x, j4.y, j4.z, j4.w };
        const float ms[4] = { m4.x, m4.y, m4.z, m4.w };

        #pragma unroll
        for (int u = 0; u < 4; ++u) {
            const float m = ms[u];
            const float4 qv = pv[js[u]];          // LDS.128 gather

            const float rpx = self.x - qv.x * m;
            const float rpy = self.y - qv.y * m;
            const float rvx = vd.x   - qv.z * m;
            const float rvy = vd.y   - qv.w * m;

            const float dpv = rpx * rvx + rpy * rvy;
            const float dvv = rvx * rvx + rvy * rvy + 1e-6f;   // ref: +1e-6
            float t = __fdividef(dpv, dvv + 1e-6f);            // ref: second +1e-6
            t = fminf(fmaxf(t, 0.0f), TAU);

            const float dx = rpx + t * rvx;
            const float dy = rpy + t * rvy;
            const float md2 = dx * dx + dy * dy;   // squared min_dist

            const float s = rpx * rpx + rpy * rpy; // squared |rel_pos|

            // reference: coll = (sqrt(md2) < thr) && (m != 0)
            //            normal = (-rpy, rpx) / (sqrt(s)+1e-6) when coll else 0
            // s == 0 (self-neighbor) => numerator 0 in reference => contribute 0.
            const bool coll = (md2 < thr2) && (m != 0.0f) && (s > 0.0f);
            const float inv = coll ? rsqrt_approx(s) : 0.0f;

            cx -= rpy * inv;
            cy += rpx * inv;
        }
    }

    out[g] = make_float2(vd.x + cx * FIX, vd.y + cy * FIX);
}

extern "C" void kernel_launch(void* const* d_in, const int* in_sizes, int n_in,
                              void* d_out, int out_size)
{
    const float2* p_cur    = (const float2*)d_in[0];
    const float2* v_cur    = (const float2*)d_in[1];
    const float2* v_desire = (const float2*)d_in[2];
    const int*    near_idx = (const int*)d_in[3];
    const float*  mask     = (const float*)d_in[4];
    const int*    thr      = (const int*)d_in[5];
    float2*       out      = (float2*)d_out;

    const int P = in_sizes[0] / 2;               // B*N pedestrians
    const int nBatches = P / NPED;               // 256
    const int blocks = nBatches * BLOCKS_PER_BATCH;

    rvo_kernel<<<blocks, THREADS>>>(p_cur, v_cur, v_desire, near_idx, mask, thr, out);
}

// round 6
// speedup vs baseline: 2.2916x; 1.5186x over previous
#include <cuda_runtime.h>

// RVOModule on GB300. B=256, N=1024, K=32.
// R6: warp owns 32 consecutive pedestrians; 8 passes, 4 peds/pass,
// 8 lanes per pedestrian. idx/mask loads fully coalesced (int4/float4 over a
// contiguous 4KB block per warp). Gathers from smem-staged batch state.
// 8-lane shuffle reduction.

#define TAU 3.0f
#define FIX 0.2f

#define NPED 1024
#define KNEI 32
#define BPB 2                 // blocks per batch
#define THREADS 512           // peds per block

__device__ __forceinline__ float rsqrt_approx(float x) {
    float r;
    asm("rsqrt.approx.f32 %0, %1;" : "=f"(r) : "f"(x));
    return r;
}

__global__ __launch_bounds__(THREADS, 2)
void rvo_kernel(const float2* __restrict__ p_cur,
                const float2* __restrict__ v_cur,
                const float2* __restrict__ v_desire,
                const int*    __restrict__ near_idx,
                const float*  __restrict__ neigh_mask,
                const int*    __restrict__ thr_ptr,
                float2*       __restrict__ out)
{
    __shared__ float4 pv[NPED];       // {p.x,p.y,v.x,v.y} whole batch, 16 KB
    __shared__ float2 vds[THREADS];   // v_desire for this block's peds, 4 KB

    const int b       = blockIdx.x / BPB;
    const int sub     = blockIdx.x % BPB;
    const int base    = b * NPED;          // global ped id of batch start
    const int pedbase = sub * THREADS;     // within-batch start of this block

    // Stage whole batch's (p,v) — coalesced float2 reads.
    #pragma unroll
    for (int i = threadIdx.x; i < NPED; i += THREADS) {
        const float2 p = p_cur[base + i];
        const float2 v = v_cur[base + i];
        pv[i] = make_float4(p.x, p.y, v.x, v.y);
    }
    // Stage this block's v_desire.
    vds[threadIdx.x] = v_desire[base + pedbase + threadIdx.x];
    __syncthreads();

    const int warp = threadIdx.x >> 5;
    const int lane = threadIdx.x & 31;
    const int grp  = lane >> 3;            // which ped (0..3) within pass
    const int q8   = lane & 7;             // which int4 of that ped's list

    const float thrF = (float)(*thr_ptr);
    const float thr2 = thrF * thrF;

    const int nb = pedbase + warp * 32;    // within-batch id of warp's first ped
    const int g0 = base + nb;              // global id of warp's first ped

    // Contiguous region: 32 peds * 32 idx = 1024 ints = 256 int4.
    const int4*   idx4 = (const int4*)  (near_idx)   + (long long)g0 * (KNEI / 4);
    const float4* msk4 = (const float4*)(neigh_mask) + (long long)g0 * (KNEI / 4);

    #pragma unroll 2
    for (int c = 0; c < 8; ++c) {
        // Coalesced: 32 lanes read 512B contiguous (4 sectors).
        const int4   j4 = idx4[c * 32 + lane];
        const float4 m4 = msk4[c * 32 + lane];

        const int pl = c * 4 + grp;        // ped offset within warp's 32
        const float4 self = pv[nb - pedbase + pedbase + pl + warp * 32 - warp * 32 + 0 ? 0 : 0]; // (placeholder avoided below)
        (void)self;
        const float4 sf = pv[nb + pl];     // broadcast within 8-lane group
        const float2 vd = vds[warp * 32 + pl];

        const int   js[4] = { j4.x, j4.y, j4.z, j4.w };
        const float ms[4] = { m4.x, m4.y, m4.z, m4.w };

        float cx = 0.0f, cy = 0.0f;

        #pragma unroll
        for (int u = 0; u < 4; ++u) {
            const float m  = ms[u];
            const float4 qv = pv[js[u]];   // LDS.128 gather

            const float rpx = sf.x - qv.x * m;
            const float rpy = sf.y - qv.y * m;
            const float rvx = vd.x - qv.z * m;
            const float rvy = vd.y - qv.w * m;

            const float dpv = rpx * rvx + rpy * rvy;
            const float dvv = rvx * rvx + rvy * rvy + 1e-6f;  // ref: +1e-6
            float t = __fdividef(dpv, dvv + 1e-6f);           // ref: second +1e-6
            t = fminf(fmaxf(t, 0.0f), TAU);

            const float dx = rpx + t * rvx;
            const float dy = rpy + t * rvy;
            const float md2 = dx * dx + dy * dy;              // min_dist^2

            const float s = rpx * rpx + rpy * rpy;            // |rel_pos|^2

            // ref: coll = (sqrt(md2)<thr) && m!=0; normal /(sqrt(s)+1e-6);
            // s==0 (self) -> numerator 0 in ref -> contributes 0.
            const bool coll = (md2 < thr2) && (m != 0.0f) && (s > 0.0f);
            const float inv = coll ? rsqrt_approx(s) : 0.0f;

            cx -= rpy * inv;
            cy += rpx * inv;
        }

        // Reduce across the 8 lanes sharing this pedestrian.
        #pragma unroll
        for (int o = 1; o < 8; o <<= 1) {
            cx += __shfl_xor_sync(0xffffffffu, cx, o);
            cy += __shfl_xor_sync(0xffffffffu, cy, o);
        }

        if (q8 == 0) {
            out[g0 + pl] = make_float2(vd.x + cx * FIX, vd.y + cy * FIX);
        }
    }
}

extern "C" void kernel_launch(void* const* d_in, const int* in_sizes, int n_in,
                              void* d_out, int out_size)
{
    const float2* p_cur    = (const float2*)d_in[0];
    const float2* v_cur    = (const float2*)d_in[1];
    const float2* v_desire = (const float2*)d_in[2];
    const int*    near_idx = (const int*)d_in[3];
    const float*  mask     = (const float*)d_in[4];
    const int*    thr      = (const int*)d_in[5];
    float2*       out      = (float2*)d_out;

    const int P = in_sizes[0] / 2;          // B*N pedestrians
    const int nBatches = P / NPED;          // 256
    const int blocks = nBatches * BPB;      // 512

    rvo_kernel<<<blocks, THREADS>>>(p_cur, v_cur, v_desire, near_idx, mask, thr, out);
}

// round 7
// speedup vs baseline: 2.3171x; 1.0111x over previous
#include <cuda_runtime.h>

// RVOModule on GB300. B=256, N=1024, K=32.
// R7 = R6 (warp owns 32 peds; 8 passes x 4 peds; 8 lanes/ped; coalesced
// int4/float4 idx+mask loads; smem-staged batch state; fast math)
// + occupancy: __launch_bounds__(512,3) and no outer unroll (regs <= 42).

#define TAU 3.0f
#define FIX 0.2f

#define NPED 1024
#define KNEI 32
#define BPB 2                 // blocks per batch
#define THREADS 512           // peds per block

__device__ __forceinline__ float rsqrt_approx(float x) {
    float r;
    asm("rsqrt.approx.f32 %0, %1;" : "=f"(r) : "f"(x));
    return r;
}

__global__ __launch_bounds__(THREADS, 3)
void rvo_kernel(const float2* __restrict__ p_cur,
                const float2* __restrict__ v_cur,
                const float2* __restrict__ v_desire,
                const int*    __restrict__ near_idx,
                const float*  __restrict__ neigh_mask,
                const int*    __restrict__ thr_ptr,
                float2*       __restrict__ out)
{
    __shared__ float4 pv[NPED];       // {p.x,p.y,v.x,v.y} whole batch, 16 KB
    __shared__ float2 vds[THREADS];   // v_desire for this block's peds, 4 KB

    const int b       = blockIdx.x / BPB;
    const int sub     = blockIdx.x % BPB;
    const int base    = b * NPED;          // global ped id of batch start
    const int pedbase = sub * THREADS;     // within-batch start of this block

    // Stage whole batch's (p,v) — coalesced float2 reads.
    #pragma unroll
    for (int i = threadIdx.x; i < NPED; i += THREADS) {
        const float2 p = p_cur[base + i];
        const float2 v = v_cur[base + i];
        pv[i] = make_float4(p.x, p.y, v.x, v.y);
    }
    // Stage this block's v_desire.
    vds[threadIdx.x] = v_desire[base + pedbase + threadIdx.x];
    __syncthreads();

    const int warp = threadIdx.x >> 5;
    const int lane = threadIdx.x & 31;
    const int grp  = lane >> 3;            // which ped (0..3) within pass
    const int q8   = lane & 7;             // which int4 of that ped's list

    const float thrF = (float)(*thr_ptr);
    const float thr2 = thrF * thrF;

    const int nb = pedbase + warp * 32;    // within-batch id of warp's first ped
    const int g0 = base + nb;              // global id of warp's first ped

    // Contiguous region: 32 peds * 32 idx = 1024 ints = 256 int4.
    const int4*   idx4 = (const int4*)  (near_idx)   + (long long)g0 * (KNEI / 4);
    const float4* msk4 = (const float4*)(neigh_mask) + (long long)g0 * (KNEI / 4);

    #pragma unroll 1
    for (int c = 0; c < 8; ++c) {
        // Coalesced: 32 lanes read 512B contiguous (4 sectors).
        const int4   j4 = idx4[c * 32 + lane];
        const float4 m4 = msk4[c * 32 + lane];

        const int pl = c * 4 + grp;        // ped offset within warp's 32
        const float4 sf = pv[nb + pl];     // broadcast within 8-lane group
        const float2 vd = vds[warp * 32 + pl];

        const int   js[4] = { j4.x, j4.y, j4.z, j4.w };
        const float ms[4] = { m4.x, m4.y, m4.z, m4.w };

        float cx = 0.0f, cy = 0.0f;

        #pragma unroll
        for (int u = 0; u < 4; ++u) {
            const float m  = ms[u];
            const float4 qv = pv[js[u]];   // LDS.128 gather

            const float rpx = sf.x - qv.x * m;
            const float rpy = sf.y - qv.y * m;
            const float rvx = vd.x - qv.z * m;
            const float rvy = vd.y - qv.w * m;

            const float dpv = rpx * rvx + rpy * rvy;
            const float dvv = rvx * rvx + rvy * rvy + 1e-6f;  // ref: +1e-6
            float t = __fdividef(dpv, dvv + 1e-6f);           // ref: second +1e-6
            t = fminf(fmaxf(t, 0.0f), TAU);

            const float dx = rpx + t * rvx;
            const float dy = rpy + t * rvy;
            const float md2 = dx * dx + dy * dy;              // min_dist^2

            const float s = rpx * rpx + rpy * rpy;            // |rel_pos|^2

            // ref: coll = (sqrt(md2)<thr) && m!=0; normal /(sqrt(s)+1e-6);
            // s==0 (self) -> numerator 0 in ref -> contributes 0.
            const bool coll = (md2 < thr2) && (m != 0.0f) && (s > 0.0f);
            const float inv = coll ? rsqrt_approx(s) : 0.0f;

            cx -= rpy * inv;
            cy += rpx * inv;
        }

        // Reduce across the 8 lanes sharing this pedestrian.
        #pragma unroll
        for (int o = 1; o < 8; o <<= 1) {
            cx += __shfl_xor_sync(0xffffffffu, cx, o);
            cy += __shfl_xor_sync(0xffffffffu, cy, o);
        }

        if (q8 == 0) {
            out[g0 + pl] = make_float2(vd.x + cx * FIX, vd.y + cy * FIX);
        }
    }
}

extern "C" void kernel_launch(void* const* d_in, const int* in_sizes, int n_in,
                              void* d_out, int out_size)
{
    const float2* p_cur    = (const float2*)d_in[0];
    const float2* v_cur    = (const float2*)d_in[1];
    const float2* v_desire = (const float2*)d_in[2];
    const int*    near_idx = (const int*)d_in[3];
    const float*  mask     = (const float*)d_in[4];
    const int*    thr      = (const int*)d_in[5];
    float2*       out      = (float2*)d_out;

    const int P = in_sizes[0] / 2;          // B*N pedestrians
    const int nBatches = P / NPED;          // 256
    const int blocks = nBatches * BPB;      // 512

    rvo_kernel<<<blocks, THREADS>>>(p_cur, v_cur, v_desire, near_idx, mask, thr, out);
}